// round 5
// baseline (speedup 1.0000x reference)
#include <cuda_runtime.h>
#include <cstdint>

// Problem constants (fixed by setup_inputs)
#define NB 8
#define NH 100
#define NT 1000
#define NTS 80000   // NT * 80
#define BLK 256
#define NH2 (NH / 2)   // 50 harmonic pairs

// mod-2pi constants
#define INV2PI 0.15915494309189535f
#define MAGIC  12582912.0f                 // 1.5 * 2^23
// fusion-independent 3-term split of 2*pi (k < 2^18):
//   HI1 = 6.25            (5-bit significand: k*HI1 exact)
//   HI2 = 17 * 2^-9       (5-bit significand: k*HI2 exact)
//   C3  = HI1 + HI2 - 2pi = +1.7817820414e-5  (r = d2 + k*C3)
#define NHI1 (-6.25f)
#define NHI2 (-0.033203125f)
#define C3   (1.7817820414e-5f)

typedef unsigned long long u64;

// ---- packed f32x2 helpers (Blackwell sm_103a) ----
__device__ __forceinline__ u64 pk2(float lo, float hi) {
    u64 r; asm("mov.b64 %0, {%1, %2};" : "=l"(r) : "f"(lo), "f"(hi)); return r;
}
__device__ __forceinline__ void upk2(float& lo, float& hi, u64 v) {
    asm("mov.b64 {%0, %1}, %2;" : "=f"(lo), "=f"(hi) : "l"(v));
}
__device__ __forceinline__ u64 add2(u64 a, u64 b) {
    u64 r; asm("add.rn.f32x2 %0, %1, %2;" : "=l"(r) : "l"(a), "l"(b)); return r;
}
__device__ __forceinline__ u64 fma2(u64 a, u64 b, u64 c) {
    u64 r; asm("fma.rn.f32x2 %0, %1, %2, %3;" : "=l"(r) : "l"(a), "l"(b), "l"(c)); return r;
}

// smem entry: one LDS.128 = two aligned u64 lane-pairs
struct __align__(16) QPair { u64 x0; u64 d; };   // (x0_h, x0_h+1), (d_h, d_h+1)

__global__ __launch_bounds__(BLK)
void HarmonicOscillator_kernel(
    const float* __restrict__ f0,   // [B,1,T]
    const float* __restrict__ hd,   // [B,H,T]
    const float* __restrict__ ps,   // [B,1,T]
    float* __restrict__ out)        // [B,Ts]
{
    __shared__ QPair q[NH2 * 5];

    const int s0 = blockIdx.x * BLK;
    const int b  = blockIdx.y;
    const int s  = s0 + threadIdx.x;

    const float R = (float)(999.0 / 79999.0);   // (T-1)/(Ts-1) rounded like jax f32

    // Block-uniform window start (i0 monotone; spans <=5 values over 256 samples)
    int j0 = (int)__fmul_rn((float)s0, R);
    if (j0 > NT - 2) j0 = NT - 2;

    // --- cooperative smem fill: 250 pair-entries ---
    {
        const float* hb = hd + (size_t)b * (NH * NT);
        for (int idx = threadIdx.x; idx < NH2 * 5; idx += BLK) {
            int h2 = idx / 5;
            int j  = idx - h2 * 5;
            int g0 = j0 + j;  if (g0 > NT - 1) g0 = NT - 1;
            int g1 = g0 + 1;  if (g1 > NT - 1) g1 = NT - 1;
            const float* r0 = hb + (2 * h2) * NT;
            const float* r1 = r0 + NT;
            float a0 = __ldg(r0 + g0), a1 = __ldg(r0 + g1);
            float b0 = __ldg(r1 + g0), b1 = __ldg(r1 + g1);
            q[idx].x0 = pk2(a0, b0);
            q[idx].d  = pk2(__fsub_rn(a1, a0), __fsub_rn(b1, b0));
        }
    }
    __syncthreads();

    if (s >= NTS) return;

    // --- per-thread interpolation coords (match jnp f32 rounding exactly) ---
    float sF  = (float)s;
    float pos = __fmul_rn(sF, R);
    int i0 = (int)pos;                   // pos >= 0 -> trunc == floor
    if (i0 > NT - 2) i0 = NT - 2;
    float w = __fsub_rn(pos, (float)i0);
    int li = i0 - j0;                    // 0..4

    // --- f0 / phase_shift interp: x0 + (x1-x0)*w, separate roundings ---
    const float* f0b = f0 + b * NT;
    const float* psb = ps + b * NT;
    float fa = __ldg(f0b + i0), fb = __ldg(f0b + i0 + 1);
    float f0u = __fadd_rn(fa, __fmul_rn(__fsub_rn(fb, fa), w));
    float pa = __ldg(psb + i0), pb = __ldg(psb + i0 + 1);
    float psu = __fadd_rn(pa, __fmul_rn(__fsub_rn(pb, pa), w));

    // base = fl(fl(C * f0u) * t), C = fl(2*pi/16000)
    const float C = (float)(2.0 * 3.14159265358979323846 / 16000.0);
    float base = __fmul_rn(__fmul_rn(C, f0u), sF);

    const QPair* qp = q + li;

    // packed loop-invariant operands
    u64 psu2  = pk2(psu, psu);
    u64 w2    = pk2(w, w);
    u64 INV2  = pk2(INV2PI, INV2PI);
    u64 MG2   = pk2(MAGIC, MAGIC);
    u64 NMG2  = pk2(-MAGIC, -MAGIC);
    u64 NH1_2 = pk2(NHI1, NHI1);
    u64 NH2_2 = pk2(NHI2, NHI2);
    u64 C3_2  = pk2(C3, C3);
    u64 acc2  = pk2(0.0f, 0.0f);

    #pragma unroll
    for (int h2 = 0; h2 < NH2; ++h2) {
        QPair v = qp[h2 * 5];                              // one LDS.128

        // scalar FMUL-imm: bit-exact fl(base*h) per lane (known-good sequence)
        float p0 = __fmul_rn(base, (float)(2 * h2 + 1));
        float p1 = __fmul_rn(base, (float)(2 * h2 + 2));
        u64 X2 = add2(pk2(p0, p1), psu2);                  // fl(p + psu), per-lane RN

        // fusion-independent 3-term reduction mod 2*pi
        u64 kb2 = fma2(X2, INV2, MG2);    // k in mantissa (±1 slack tolerated)
        u64 kf2 = add2(kb2, NMG2);        // exact
        u64 d1  = fma2(kf2, NH1_2, X2);   // k*6.25 exact product, diff exactly representable
        u64 d2  = fma2(kf2, NH2_2, d1);   // k*HI2 exact product, diff exactly representable
        u64 r2  = fma2(kf2, C3_2, d2);    // tiny correction: ~2e-7 err fused or split

        float r0, r1; upk2(r0, r1, r2);
        u64 s2 = pk2(__sinf(r0), __sinf(r1));              // 2x MUFU.SIN

        u64 hdu2 = fma2(v.d, w2, v.x0);                    // interp (tolerant)
        acc2 = fma2(s2, hdu2, acc2);                       // accumulate (tolerant)
    }

    float a0, a1; upk2(a0, a1, acc2);
    out[(size_t)b * NTS + s] = __fadd_rn(a0, a1);
}

extern "C" void kernel_launch(void* const* d_in, const int* in_sizes, int n_in,
                              void* d_out, int out_size) {
    const float* f0 = (const float*)d_in[0];
    const float* hd = (const float*)d_in[1];
    const float* ps = (const float*)d_in[2];
    float* out = (float*)d_out;

    dim3 block(BLK);
    dim3 grid((NTS + BLK - 1) / BLK, NB);
    HarmonicOscillator_kernel<<<grid, block>>>(f0, hd, ps, out);
}